// round 10
// baseline (speedup 1.0000x reference)
#include <cuda_runtime.h>
#include <cuda_fp16.h>

// LBP forward: out = 7.5 + 0.5 * sum_p 2^p * tanh(5*(samp_p - cen_p))
//
// Stage: THREE pre-shifted, zero-padded fp16 copies scaled by 5 (PW=72: 8 left
// pad cols so every 8-wide span at col w+8 (w multiple of 8) is 16B-aligned):
//   copy_s[pl][r][j] = 5 * x[pl][r-1][j-9+s],  s in {0,1,2}, zero outside.
// Main: thread = (n, f, 4-row block, 8-wide span) = 32 outputs.
//   center  = copy_1 at (r+1,   w+8)  -> one aligned LDG.128 per row
//   sample  = copy_{dx+1} at (r+1+dy, w+8) -> one aligned LDG.128 per row
//   zero bounds checks, zero shift ALU; (dy,dx)==(0,0) taps skipped.

#define N_  32
#define D_  64
#define H_  56
#define W_  56
#define F_  128
#define P_  4
#define HW_ (H_ * W_)
#define PW  72
#define PH  58
#define PPLANE (PW * PH)                  // 4176 halfs (8352 B, 16B-divisible)
#define NPLANES (N_ * D_)                 // 2048
#define SVOL ((size_t)NPLANES * PPLANE)   // halfs per copy

__device__ __align__(16) __half g3[3 * NPLANES * PPLANE];   // 51.3 MB

// ---------------- stage ----------------
#define CH_ 9                               // 8-col chunks per padded row
#define STAGE_TOTAL (NPLANES * PH * CH_)    // 1,069,056 threads

__global__ __launch_bounds__(256) void lbp_stage_kernel(const float* __restrict__ in)
{
    int idx = blockIdx.x * 256 + threadIdx.x;
    if (idx >= STAGE_TOTAL) return;
    int k  = idx % CH_;            // chunk: padded cols 8k..8k+7
    int t  = idx / CH_;
    int r  = t % PH;
    int pl = t / PH;
    int row = r - 1;

    float wv[10];                  // x cols 8k-9 .. 8k
#pragma unroll
    for (int i = 0; i < 10; i++) wv[i] = 0.f;

    if (row >= 0 && row < H_) {
        const float* __restrict__ rp = in + (size_t)pl * HW_ + row * W_;
        if (k >= 2) wv[0] = rp[8 * k - 9];
        if (k >= 1) {
            float4 a = *reinterpret_cast<const float4*>(rp + 8 * k - 8);
            wv[1] = a.x; wv[2] = a.y; wv[3] = a.z; wv[4] = a.w;
            float4 b = *reinterpret_cast<const float4*>(rp + 8 * k - 4);
            wv[5] = b.x; wv[6] = b.y; wv[7] = b.z; wv[8] = b.w;
        }
        if (k <= 6) wv[9] = rp[8 * k];
    }

#pragma unroll
    for (int s = 0; s < 3; s++) {
        __half2 h[4];
#pragma unroll
        for (int q = 0; q < 4; q++)
            h[q] = __floats2half2_rn(5.f * wv[s + 2 * q], 5.f * wv[s + 2 * q + 1]);
        __half* dst = g3 + (size_t)s * SVOL + (size_t)pl * PPLANE + r * PW + 8 * k;
        *reinterpret_cast<uint4*>(dst) = *reinterpret_cast<uint4*>(h);
    }
}

// ---------------- main ----------------
__device__ __forceinline__ __half2 tanh_h2u(unsigned v) {
    asm("tanh.approx.f16x2 %0, %0;" : "+r"(v));
    return *reinterpret_cast<__half2*>(&v);
}

#define RB_ 14     // 4-row blocks
#define WS_ 7      // 8-wide spans
#define TOTAL_ (N_ * F_ * RB_ * WS_)   // 401,408 threads

__global__ __launch_bounds__(256) void lbp_main_kernel(
    const int* __restrict__ kern,   // (F,P,2)
    const int* __restrict__ pm,     // (F,P)
    float*     __restrict__ out)
{
    int idx = blockIdx.x * 256 + threadIdx.x;
    if (idx >= TOTAL_) return;

    int ws = idx % WS_;
    int t  = idx / WS_;
    int rb = t % RB_;
    t /= RB_;
    int f  = t & (F_ - 1);
    int n  = t >> 7;

    int r0 = rb * 4;
    int w  = ws * 8;

    int4 pmv = *reinterpret_cast<const int4*>(pm + f * P_);
    int4 k01 = *reinterpret_cast<const int4*>(kern + f * P_ * 2);
    int4 k23 = *reinterpret_cast<const int4*>(kern + f * P_ * 2 + 4);
    int cs[4]  = {pmv.x, pmv.y, pmv.z, pmv.w};
    int dys[4] = {k01.x - 1, k01.z - 1, k23.x - 1, k23.z - 1};
    int dxs[4] = {k01.y - 1, k01.w - 1, k23.y - 1, k23.w - 1};

    const size_t nbase = (size_t)n * D_ * PPLANE;
    const int    rcoff = (r0 + 1) * PW + (w + 8);    // 16B-aligned column

    __half2 z = __floats2half2_rn(0.f, 0.f);
    __half2 acc[16];                 // [row j][4 half2]
#pragma unroll
    for (int j = 0; j < 16; j++) acc[j] = z;

#pragma unroll
    for (int p = 0; p < P_; p++) {
        int dy = dys[p], dx = dxs[p];
        if ((dy | dx) == 0) continue;            // tanh(0) == 0

        const __half* __restrict__ cp =
            g3 + SVOL + nbase + (size_t)cs[p] * PPLANE + rcoff;
        const __half* __restrict__ sp =
            g3 + (size_t)(dx + 1) * SVOL + nbase + (size_t)cs[p] * PPLANE
               + rcoff + dy * PW;

        float wpf = 0.5f * (float)(1 << p);
        __half2 wp2 = __floats2half2_rn(wpf, wpf);

#pragma unroll
        for (int j = 0; j < 4; j++) {
            uint4 cv = *reinterpret_cast<const uint4*>(cp + j * PW);
            uint4 sv = *reinterpret_cast<const uint4*>(sp + j * PW);
            __half2 d0 = __hsub2(*reinterpret_cast<__half2*>(&sv.x),
                                 *reinterpret_cast<__half2*>(&cv.x));
            __half2 d1 = __hsub2(*reinterpret_cast<__half2*>(&sv.y),
                                 *reinterpret_cast<__half2*>(&cv.y));
            __half2 d2 = __hsub2(*reinterpret_cast<__half2*>(&sv.z),
                                 *reinterpret_cast<__half2*>(&cv.z));
            __half2 d3 = __hsub2(*reinterpret_cast<__half2*>(&sv.w),
                                 *reinterpret_cast<__half2*>(&cv.w));
            acc[j * 4 + 0] = __hfma2(wp2, tanh_h2u(*reinterpret_cast<unsigned*>(&d0)), acc[j * 4 + 0]);
            acc[j * 4 + 1] = __hfma2(wp2, tanh_h2u(*reinterpret_cast<unsigned*>(&d1)), acc[j * 4 + 1]);
            acc[j * 4 + 2] = __hfma2(wp2, tanh_h2u(*reinterpret_cast<unsigned*>(&d2)), acc[j * 4 + 2]);
            acc[j * 4 + 3] = __hfma2(wp2, tanh_h2u(*reinterpret_cast<unsigned*>(&d3)), acc[j * 4 + 3]);
        }
    }

    float* o = out + ((size_t)(n * F_ + f) * HW_ + r0 * W_ + w);
#pragma unroll
    for (int j = 0; j < 4; j++) {
        float2 q0 = __half22float2(acc[j * 4 + 0]);
        float2 q1 = __half22float2(acc[j * 4 + 1]);
        float2 q2 = __half22float2(acc[j * 4 + 2]);
        float2 q3 = __half22float2(acc[j * 4 + 3]);
        float* orow = o + j * W_;
        *reinterpret_cast<float4*>(orow) =
            make_float4(7.5f + q0.x, 7.5f + q0.y, 7.5f + q1.x, 7.5f + q1.y);
        *reinterpret_cast<float4*>(orow + 4) =
            make_float4(7.5f + q2.x, 7.5f + q2.y, 7.5f + q3.x, 7.5f + q3.y);
    }
}

extern "C" void kernel_launch(void* const* d_in, const int* in_sizes, int n_in,
                              void* d_out, int out_size)
{
    const float* in   = (const float*)d_in[0];
    const int*   kern = (const int*)d_in[1];
    const int*   pm   = (const int*)d_in[2];
    float*       out  = (float*)d_out;

    lbp_stage_kernel<<<(STAGE_TOTAL + 255) / 256, 256>>>(in);
    lbp_main_kernel<<<(TOTAL_ + 255) / 256, 256>>>(kern, pm, out);
}

// round 11
// speedup vs baseline: 1.1789x; 1.1789x over previous
#include <cuda_runtime.h>
#include <cuda_fp16.h>

// LBP forward: out = 7.5 + 0.5 * sum_p 2^p * tanh(5*(samp_p - cen_p))
//
// Stage: TWO zero-padded fp16 copies scaled by 5 (PW=64: 4 left pad cols):
//   copy1[pl][r][j] = 5 * x[pl][r-1][j-4]   (centers, dx=0 samples)
//   copyB[pl][r][j] = 5 * x[pl][r-1][j-5]   (dx=-1 aligned; dx=+1 at +2 cols)
// Main: thread = (n, f, 4-row block, 4-col quad) = 16 outputs (R8 config).
//   center        : copy1 (r+1,   w+4)      -> aligned LDG.64 per row
//   sample dx=0   : copy1 (r+1+dy, w+4)     -> aligned LDG.64
//   sample dx=-1  : copyB (r+1+dy, w+4)     -> aligned LDG.64
//   sample dx=+1  : copyB (r+1+dy, w+6)     -> two LDG.32
//   zero bounds checks; (dy,dx)==(0,0) taps skipped (tanh(0)=0).

#define N_  32
#define D_  64
#define H_  56
#define W_  56
#define F_  128
#define P_  4
#define HW_ (H_ * W_)
#define PW  64
#define PH  58
#define PPLANE (PW * PH)                  // 3712 halfs
#define NPLANES (N_ * D_)                 // 2048
#define SVOL ((size_t)NPLANES * PPLANE)   // halfs per copy

__device__ __align__(16) __half g2[2 * NPLANES * PPLANE];   // 30.4 MB

// ---------------- stage ----------------
#define STAGE_TOTAL (NPLANES * PH * 8)    // one thread per 8-half chunk (950,272)

__global__ __launch_bounds__(256) void lbp_stage_kernel(const float* __restrict__ in)
{
    int idx = blockIdx.x * 256 + threadIdx.x;
    if (idx >= STAGE_TOTAL) return;
    int k  = idx & 7;             // chunk: padded cols 8k..8k+7
    int t  = idx >> 3;
    int r  = t % PH;
    int pl = t / PH;
    int row = r - 1;

    float wv[12];                 // wv[i] = x[8k-8+i], i=0..11
#pragma unroll
    for (int i = 0; i < 12; i++) wv[i] = 0.f;

    if (row >= 0 && row < H_) {
        const float* __restrict__ rp = in + (size_t)pl * HW_ + row * W_;
        if (k >= 1) {
            float4 a = *reinterpret_cast<const float4*>(rp + 8 * k - 8);
            wv[0] = a.x; wv[1] = a.y; wv[2] = a.z; wv[3] = a.w;
            float4 b = *reinterpret_cast<const float4*>(rp + 8 * k - 4);
            wv[4] = b.x; wv[5] = b.y; wv[6] = b.z; wv[7] = b.w;
        }
        if (k <= 6) {
            float4 c = *reinterpret_cast<const float4*>(rp + 8 * k);
            wv[8] = c.x; wv[9] = c.y; wv[10] = c.z; wv[11] = c.w;
        }
    }

    // copy1[8k+t] = 5*x[8k-4+t] = 5*wv[4+t];  copyB[8k+t] = 5*wv[3+t]
    __half2 h1[4], hB[4];
#pragma unroll
    for (int q = 0; q < 4; q++) {
        h1[q] = __floats2half2_rn(5.f * wv[4 + 2 * q], 5.f * wv[5 + 2 * q]);
        hB[q] = __floats2half2_rn(5.f * wv[3 + 2 * q], 5.f * wv[4 + 2 * q]);
    }
    size_t off = (size_t)pl * PPLANE + r * PW + 8 * k;
    *reinterpret_cast<uint4*>(g2 + off)        = *reinterpret_cast<uint4*>(h1);
    *reinterpret_cast<uint4*>(g2 + SVOL + off) = *reinterpret_cast<uint4*>(hB);
}

// ---------------- main ----------------
__device__ __forceinline__ __half2 tanh_h2u(unsigned v) {
    asm("tanh.approx.f16x2 %0, %0;" : "+r"(v));
    return *reinterpret_cast<__half2*>(&v);
}

#define RB_ 14     // 4-row blocks
#define WQ_ 14     // 4-col quads
#define TOTAL_ (N_ * F_ * RB_ * WQ_)   // 802,816 threads

__global__ __launch_bounds__(256) void lbp_main_kernel(
    const int* __restrict__ kern,   // (F,P,2)
    const int* __restrict__ pm,     // (F,P)
    float*     __restrict__ out)
{
    int idx = blockIdx.x * 256 + threadIdx.x;
    if (idx >= TOTAL_) return;

    int wq = idx % WQ_;
    int t  = idx / WQ_;
    int rb = t % RB_;
    t /= RB_;
    int f  = t & (F_ - 1);
    int n  = t >> 7;

    int r0 = rb * 4;
    int w  = wq * 4;

    int4 pmv = *reinterpret_cast<const int4*>(pm + f * P_);
    int4 k01 = *reinterpret_cast<const int4*>(kern + f * P_ * 2);
    int4 k23 = *reinterpret_cast<const int4*>(kern + f * P_ * 2 + 4);
    int cs[4]  = {pmv.x, pmv.y, pmv.z, pmv.w};
    int dys[4] = {k01.x - 1, k01.z - 1, k23.x - 1, k23.z - 1};
    int dxs[4] = {k01.y - 1, k01.w - 1, k23.y - 1, k23.w - 1};

    const size_t nbase = (size_t)n * D_ * PPLANE;
    const int    rcoff = (r0 + 1) * PW + (w + 4);   // padded (row,col), 8B aligned

    __half2 z = __floats2half2_rn(0.f, 0.f);
    __half2 acc[8];                 // [row j][lo/hi half2]
#pragma unroll
    for (int j = 0; j < 8; j++) acc[j] = z;

#pragma unroll
    for (int p = 0; p < P_; p++) {
        int dy = dys[p], dx = dxs[p];
        if ((dy | dx) == 0) continue;            // tanh(0) == 0

        const __half* __restrict__ cp = g2 + nbase + (size_t)cs[p] * PPLANE + rcoff;

        // sample base: dx==0 -> copy1; dx!=0 -> copyB (col +2 when dx=+1)
        const __half* __restrict__ sp =
            g2 + (dx != 0 ? SVOL : (size_t)0) + nbase + (size_t)cs[p] * PPLANE
               + rcoff + dy * PW + (dx > 0 ? 2 : 0);

        float wpf = 0.5f * (float)(1 << p);
        __half2 wp2 = __floats2half2_rn(wpf, wpf);

        if (dx > 0) {
#pragma unroll
            for (int j = 0; j < 4; j++) {
                uint2 cv = *reinterpret_cast<const uint2*>(cp + j * PW);
                unsigned sv0 = *reinterpret_cast<const unsigned*>(sp + j * PW);
                unsigned sv1 = *reinterpret_cast<const unsigned*>(sp + j * PW + 2);
                __half2 d0 = __hsub2(*reinterpret_cast<__half2*>(&sv0),
                                     *reinterpret_cast<__half2*>(&cv.x));
                __half2 d1 = __hsub2(*reinterpret_cast<__half2*>(&sv1),
                                     *reinterpret_cast<__half2*>(&cv.y));
                acc[j * 2 + 0] = __hfma2(wp2, tanh_h2u(*reinterpret_cast<unsigned*>(&d0)), acc[j * 2 + 0]);
                acc[j * 2 + 1] = __hfma2(wp2, tanh_h2u(*reinterpret_cast<unsigned*>(&d1)), acc[j * 2 + 1]);
            }
        } else {
#pragma unroll
            for (int j = 0; j < 4; j++) {
                uint2 cv = *reinterpret_cast<const uint2*>(cp + j * PW);
                uint2 sv = *reinterpret_cast<const uint2*>(sp + j * PW);
                __half2 d0 = __hsub2(*reinterpret_cast<__half2*>(&sv.x),
                                     *reinterpret_cast<__half2*>(&cv.x));
                __half2 d1 = __hsub2(*reinterpret_cast<__half2*>(&sv.y),
                                     *reinterpret_cast<__half2*>(&cv.y));
                acc[j * 2 + 0] = __hfma2(wp2, tanh_h2u(*reinterpret_cast<unsigned*>(&d0)), acc[j * 2 + 0]);
                acc[j * 2 + 1] = __hfma2(wp2, tanh_h2u(*reinterpret_cast<unsigned*>(&d1)), acc[j * 2 + 1]);
            }
        }
    }

    float* o = out + ((size_t)(n * F_ + f) * HW_ + r0 * W_ + w);
#pragma unroll
    for (int j = 0; j < 4; j++) {
        float2 lo = __half22float2(acc[j * 2 + 0]);
        float2 hi = __half22float2(acc[j * 2 + 1]);
        *reinterpret_cast<float4*>(o + j * W_) =
            make_float4(7.5f + lo.x, 7.5f + lo.y, 7.5f + hi.x, 7.5f + hi.y);
    }
}

extern "C" void kernel_launch(void* const* d_in, const int* in_sizes, int n_in,
                              void* d_out, int out_size)
{
    const float* in   = (const float*)d_in[0];
    const int*   kern = (const int*)d_in[1];
    const int*   pm   = (const int*)d_in[2];
    float*       out  = (float*)d_out;

    lbp_stage_kernel<<<(STAGE_TOTAL + 255) / 256, 256>>>(in);
    lbp_main_kernel<<<(TOTAL_ + 255) / 256, 256>>>(kern, pm, out);
}

// round 12
// speedup vs baseline: 1.2468x; 1.0576x over previous
#include <cuda_runtime.h>
#include <cuda_fp16.h>

// LBP forward: out = 7.5 + 0.5 * sum_p 2^p * tanh(5*(samp_p - cen_p))
//
// Stage (unchanged from R11): TWO zero-padded fp16 copies scaled by 5 (PW=64):
//   copy1[pl][r][j] = 5 * x[pl][r-1][j-4]   (centers, dx=0 samples)
//   copyB[pl][r][j] = 5 * x[pl][r-1][j-5]   (dx=-1 at +0; dx=+1 at +2 cols)
// Main: thread = (n, f, 4-row block, 4-col quad) = 16 outputs.
//   BRANCHLESS + UNIFORM: every tap-row is 1 aligned LDG.64 (center)
//   + 2 LDG.32 (sample, 4B-aligned for every dx). Null taps load the center
//   address again (L1 hit) and add tanh(0)=0. Loads for all 4 taps of a row
//   are issued back-to-back (MLP=12) before any math -> L2 latency hidden.

#define N_  32
#define D_  64
#define H_  56
#define W_  56
#define F_  128
#define P_  4
#define HW_ (H_ * W_)
#define PW  64
#define PH  58
#define PPLANE (PW * PH)                  // 3712 halfs
#define NPLANES (N_ * D_)                 // 2048
#define SVOL (NPLANES * PPLANE)           // 7,602,176 halfs per copy (fits int)

__device__ __align__(16) __half g2[2 * NPLANES * PPLANE];   // 30.4 MB

// ---------------- stage ----------------
#define STAGE_TOTAL (NPLANES * PH * 8)

__global__ __launch_bounds__(256) void lbp_stage_kernel(const float* __restrict__ in)
{
    int idx = blockIdx.x * 256 + threadIdx.x;
    if (idx >= STAGE_TOTAL) return;
    int k  = idx & 7;
    int t  = idx >> 3;
    int r  = t % PH;
    int pl = t / PH;
    int row = r - 1;

    float wv[12];                 // wv[i] = x[8k-8+i]
#pragma unroll
    for (int i = 0; i < 12; i++) wv[i] = 0.f;

    if (row >= 0 && row < H_) {
        const float* __restrict__ rp = in + (size_t)pl * HW_ + row * W_;
        if (k >= 1) {
            float4 a = *reinterpret_cast<const float4*>(rp + 8 * k - 8);
            wv[0] = a.x; wv[1] = a.y; wv[2] = a.z; wv[3] = a.w;
            float4 b = *reinterpret_cast<const float4*>(rp + 8 * k - 4);
            wv[4] = b.x; wv[5] = b.y; wv[6] = b.z; wv[7] = b.w;
        }
        if (k <= 6) {
            float4 c = *reinterpret_cast<const float4*>(rp + 8 * k);
            wv[8] = c.x; wv[9] = c.y; wv[10] = c.z; wv[11] = c.w;
        }
    }

    __half2 h1[4], hB[4];
#pragma unroll
    for (int q = 0; q < 4; q++) {
        h1[q] = __floats2half2_rn(5.f * wv[4 + 2 * q], 5.f * wv[5 + 2 * q]);
        hB[q] = __floats2half2_rn(5.f * wv[3 + 2 * q], 5.f * wv[4 + 2 * q]);
    }
    size_t off = (size_t)pl * PPLANE + r * PW + 8 * k;
    *reinterpret_cast<uint4*>(g2 + off)                 = *reinterpret_cast<uint4*>(h1);
    *reinterpret_cast<uint4*>(g2 + (size_t)SVOL + off)  = *reinterpret_cast<uint4*>(hB);
}

// ---------------- main ----------------
__device__ __forceinline__ __half2 tanh_h2u(unsigned v) {
    asm("tanh.approx.f16x2 %0, %0;" : "+r"(v));
    return *reinterpret_cast<__half2*>(&v);
}

#define RB_ 14     // 4-row blocks
#define WQ_ 14     // 4-col quads
#define TOTAL_ (N_ * F_ * RB_ * WQ_)   // 802,816 threads

__global__ __launch_bounds__(256, 6) void lbp_main_kernel(
    const int* __restrict__ kern,   // (F,P,2)
    const int* __restrict__ pm,     // (F,P)
    float*     __restrict__ out)
{
    int idx = blockIdx.x * 256 + threadIdx.x;
    if (idx >= TOTAL_) return;

    int wq = idx % WQ_;
    int t  = idx / WQ_;
    int rb = t % RB_;
    t /= RB_;
    int f  = t & (F_ - 1);
    int n  = t >> 7;

    int r0 = rb * 4;
    int w  = wq * 4;

    int4 pmv = *reinterpret_cast<const int4*>(pm + f * P_);
    int4 k01 = *reinterpret_cast<const int4*>(kern + f * P_ * 2);
    int4 k23 = *reinterpret_cast<const int4*>(kern + f * P_ * 2 + 4);
    int cs[4]  = {pmv.x, pmv.y, pmv.z, pmv.w};
    int dys[4] = {k01.x - 1, k01.z - 1, k23.x - 1, k23.z - 1};
    int dxs[4] = {k01.y - 1, k01.w - 1, k23.y - 1, k23.w - 1};

    const int nbase = n * D_ * PPLANE;
    const int rcoff = (r0 + 1) * PW + (w + 4);    // 8B-aligned column

    // 32-bit offsets into g2 for center and sample of each tap (branchless).
    int coff[4], soff[4];
#pragma unroll
    for (int p = 0; p < P_; p++) {
        int dx = dxs[p], dy = dys[p];
        int pb = nbase + cs[p] * PPLANE + rcoff;
        coff[p] = pb;
        // dx==0 -> copy1 @ +0 ; dx==-1 -> copyB @ +0 ; dx==+1 -> copyB @ +2
        soff[p] = pb + dy * PW + ((dx != 0) ? SVOL : 0) + ((dx > 0) ? 2 : 0);
    }

    __half2 z = __floats2half2_rn(0.f, 0.f);
    __half2 acc[8];
#pragma unroll
    for (int j = 0; j < 8; j++) acc[j] = z;

    const __half2 wp2s[4] = {
        __floats2half2_rn(0.5f, 0.5f), __floats2half2_rn(1.f, 1.f),
        __floats2half2_rn(2.f, 2.f),   __floats2half2_rn(4.f, 4.f)
    };

#pragma unroll
    for (int j = 0; j < 4; j++) {
        // batch ALL loads for this row (12 independent LDGs -> MLP 12)
        uint2    cv[4];
        unsigned sa[4], sb[4];
#pragma unroll
        for (int p = 0; p < P_; p++) {
            cv[p] = *reinterpret_cast<const uint2*>(g2 + coff[p] + j * PW);
            sa[p] = *reinterpret_cast<const unsigned*>(g2 + soff[p] + j * PW);
            sb[p] = *reinterpret_cast<const unsigned*>(g2 + soff[p] + j * PW + 2);
        }
#pragma unroll
        for (int p = 0; p < P_; p++) {
            __half2 d0 = __hsub2(*reinterpret_cast<__half2*>(&sa[p]),
                                 *reinterpret_cast<__half2*>(&cv[p].x));
            __half2 d1 = __hsub2(*reinterpret_cast<__half2*>(&sb[p]),
                                 *reinterpret_cast<__half2*>(&cv[p].y));
            acc[j * 2 + 0] = __hfma2(wp2s[p], tanh_h2u(*reinterpret_cast<unsigned*>(&d0)), acc[j * 2 + 0]);
            acc[j * 2 + 1] = __hfma2(wp2s[p], tanh_h2u(*reinterpret_cast<unsigned*>(&d1)), acc[j * 2 + 1]);
        }
    }

    float* o = out + ((size_t)(n * F_ + f) * HW_ + r0 * W_ + w);
#pragma unroll
    for (int j = 0; j < 4; j++) {
        float2 lo = __half22float2(acc[j * 2 + 0]);
        float2 hi = __half22float2(acc[j * 2 + 1]);
        *reinterpret_cast<float4*>(o + j * W_) =
            make_float4(7.5f + lo.x, 7.5f + lo.y, 7.5f + hi.x, 7.5f + hi.y);
    }
}

extern "C" void kernel_launch(void* const* d_in, const int* in_sizes, int n_in,
                              void* d_out, int out_size)
{
    const float* in   = (const float*)d_in[0];
    const int*   kern = (const int*)d_in[1];
    const int*   pm   = (const int*)d_in[2];
    float*       out  = (float*)d_out;

    lbp_stage_kernel<<<(STAGE_TOTAL + 255) / 256, 256>>>(in);
    lbp_main_kernel<<<(TOTAL_ + 255) / 256, 256>>>(kern, pm, out);
}